// round 2
// baseline (speedup 1.0000x reference)
#include <cuda_runtime.h>
#include <math.h>

#define BB   32
#define NN   100
#define HH   128
#define BIN  16
#define EE   20000

// Scratch (allocation-free rule: __device__ globals)
__device__ float d_P[BB * NN * HH];   // P[b,n,k] = l[b,n]·W_apair[:,k] + 0.5*b_binary[k]
__device__ float d_G[BB * NN * HH];   // global_feats[b,i,h]

// ---------------------------------------------------------------------------
// Kernel A: P[b,n,k] = sum_h lf[b,n,h] * Wap[h,k] + 0.5*bb[k]
// One block per (b,n); 128 threads (thread = k).
// ---------------------------------------------------------------------------
__global__ __launch_bounds__(128) void kA(const float* __restrict__ lf,
                                          const float* __restrict__ Wap,
                                          const float* __restrict__ bb) {
    const int bn = blockIdx.x;
    const int k  = threadIdx.x;
    __shared__ float row[HH];
    row[k] = lf[(size_t)bn * HH + k];
    __syncthreads();

    float a0 = 0.5f * bb[k];
    float a1 = 0.f, a2 = 0.f, a3 = 0.f;
    #pragma unroll 4
    for (int h = 0; h < HH; h += 4) {
        a0 = fmaf(row[h + 0], Wap[(h + 0) * HH + k], a0);
        a1 = fmaf(row[h + 1], Wap[(h + 1) * HH + k], a1);
        a2 = fmaf(row[h + 2], Wap[(h + 2) * HH + k], a2);
        a3 = fmaf(row[h + 3], Wap[(h + 3) * HH + k], a3);
    }
    d_P[(size_t)bn * HH + k] = (a0 + a1) + (a2 + a3);
}

// ---------------------------------------------------------------------------
// Kernel B: for each (b,i): att scores over j and global_feats accumulation.
// One block per (b,i); 4 warps; warp w handles j = w, w+4, ...
// Lane l owns k in {4l .. 4l+3}.
// ---------------------------------------------------------------------------
__global__ __launch_bounds__(128, 4) void kB(const float* __restrict__ lf,
                                             const float* __restrict__ bin,
                                             const float* __restrict__ Wb,
                                             const float* __restrict__ Watt,
                                             const float* __restrict__ batt) {
    const int bi  = blockIdx.x;            // b*NN + i
    const int tid = threadIdx.x;
    const int w   = tid >> 5;
    const int l   = tid & 31;
    const int k0  = l << 2;                // 4*l

    __shared__ float4 bin_sh[NN * BIN / 4];   // 1600 floats = 6.4 KB
    __shared__ float  red[4][HH];             // cross-warp g reduction

    // Stage bin[b,i,:,:] (coalesced float4)
    {
        const float4* src = (const float4*)(bin + (size_t)bi * NN * BIN);
        #pragma unroll
        for (int t = tid; t < NN * BIN / 4; t += 128) bin_sh[t] = src[t];
    }

    // Register-resident weights: W_binary column quad (16x4) + W_att quad
    float wb[BIN][4];
    #pragma unroll
    for (int c = 0; c < BIN; ++c) {
        float4 v = *(const float4*)(Wb + c * HH + k0);
        wb[c][0] = v.x; wb[c][1] = v.y; wb[c][2] = v.z; wb[c][3] = v.w;
    }
    const float4 wa    = *(const float4*)(Watt + k0);
    const float  batt0 = batt[0];

    const int    b     = bi / NN;
    const float* Pbase = d_P + (size_t)b * NN * HH;
    const float* Lbase = lf  + (size_t)b * NN * HH;
    const float4 pi    = *(const float4*)(d_P + (size_t)bi * HH + k0);

    float g0 = 0.f, g1 = 0.f, g2 = 0.f, g3 = 0.f;

    __syncthreads();   // bin_sh ready

    for (int j = w; j < NN; j += 4) {
        // 16 binary features for this (b,i,j): SMEM broadcast
        const float4 c0 = bin_sh[j * 4 + 0];
        const float4 c1 = bin_sh[j * 4 + 1];
        const float4 c2 = bin_sh[j * 4 + 2];
        const float4 c3 = bin_sh[j * 4 + 3];
        const float bc[BIN] = { c0.x, c0.y, c0.z, c0.w,
                                c1.x, c1.y, c1.z, c1.w,
                                c2.x, c2.y, c2.z, c2.w,
                                c3.x, c3.y, c3.z, c3.w };

        const float4 pj = *(const float4*)(Pbase + (size_t)j * HH + k0);
        const float4 lj = *(const float4*)(Lbase + (size_t)j * HH + k0);

        float f0 = pi.x + pj.x;
        float f1 = pi.y + pj.y;
        float f2 = pi.z + pj.z;
        float f3 = pi.w + pj.w;
        #pragma unroll
        for (int c = 0; c < BIN; ++c) {
            f0 = fmaf(bc[c], wb[c][0], f0);
            f1 = fmaf(bc[c], wb[c][1], f1);
            f2 = fmaf(bc[c], wb[c][2], f2);
            f3 = fmaf(bc[c], wb[c][3], f3);
        }
        f0 = fmaxf(f0, 0.f); f1 = fmaxf(f1, 0.f);
        f2 = fmaxf(f2, 0.f); f3 = fmaxf(f3, 0.f);

        // att dot: partial over this lane's 4 k, then warp reduce (full 128-k sum)
        float part = f0 * wa.x + f1 * wa.y + f2 * wa.z + f3 * wa.w;
        #pragma unroll
        for (int o = 16; o > 0; o >>= 1)
            part += __shfl_xor_sync(0xFFFFFFFFu, part, o);

        const float s = 1.f / (1.f + __expf(-(part + batt0)));

        g0 = fmaf(s, lj.x, g0);
        g1 = fmaf(s, lj.y, g1);
        g2 = fmaf(s, lj.z, g2);
        g3 = fmaf(s, lj.w, g3);
    }

    // Cross-warp reduction of g, then store global_feats
    red[w][k0 + 0] = g0;
    red[w][k0 + 1] = g1;
    red[w][k0 + 2] = g2;
    red[w][k0 + 3] = g3;
    __syncthreads();
    d_G[(size_t)bi * HH + tid] =
        (red[0][tid] + red[1][tid]) + (red[2][tid] + red[3][tid]);
}

// ---------------------------------------------------------------------------
// Kernel C: gather epilogue.
// out[0 : E*H]       = local_pair_g[e,h] = lf[b,i,h] + lf[b,j,h]
// out[E*H : 2*E*H]   = global_pair[e,h]  = G[b,i,h]  + G[b,j,h]
// Indices are int32 (JAX x64-disabled downcasts jnp.int64 -> int32).
// Clamps are diagnostic: wrong-dtype theory => huge rel_err, not IMA.
// ---------------------------------------------------------------------------
__global__ __launch_bounds__(128) void kC(const float* __restrict__ lf,
                                          const int* __restrict__ idx,
                                          float* __restrict__ out) {
    const int e = blockIdx.x;
    const int h = threadIdx.x;
    int b = idx[e * 3 + 0];
    int i = idx[e * 3 + 1];
    int j = idx[e * 3 + 2];
    b = min(max(b, 0), BB - 1);
    i = min(max(i, 0), NN - 1);
    j = min(max(j, 0), NN - 1);

    const size_t ri = ((size_t)b * NN + i) * HH;
    const size_t rj = ((size_t)b * NN + j) * HH;

    out[(size_t)e * HH + h]                    = lf[ri + h] + lf[rj + h];
    out[(size_t)EE * HH + (size_t)e * HH + h]  = d_G[ri + h] + d_G[rj + h];
}

// ---------------------------------------------------------------------------
extern "C" void kernel_launch(void* const* d_in, const int* in_sizes, int n_in,
                              void* d_out, int out_size) {
    const float* lf   = (const float*)d_in[0];   // [B,N,H]
    const float* bin  = (const float*)d_in[1];   // [B,N,N,BIN]
    const int*   sidx = (const int*)d_in[2];     // [E,3] int32
    const float* Wap  = (const float*)d_in[3];   // [H,H]
    const float* Wb   = (const float*)d_in[4];   // [BIN,H]
    const float* bb   = (const float*)d_in[5];   // [H]
    const float* Watt = (const float*)d_in[6];   // [H,1]
    const float* batt = (const float*)d_in[7];   // [1]
    float*       out  = (float*)d_out;

    kA<<<BB * NN, 128>>>(lf, Wap, bb);
    kB<<<BB * NN, 128>>>(lf, bin, Wb, Watt, batt);
    kC<<<EE, 128>>>(lf, sidx, out);
}